// round 10
// baseline (speedup 1.0000x reference)
#include <cuda_runtime.h>

// Problem dims
#define N_  20000
#define K_  20
#define T_  50
#define D_  200
#define T2  25            // t-pairs (f32x2 over fastest axis)
#define NT  16            // n rows per block
#define NNN 2             // n rows per compute thread (theta in regs: 2*20 u64)
#define GRP 8             // NT/NNN
#define CTH 200           // GRP*T2 compute threads per half
#define HALF 224          // 7 warps per half
#define BLK 448
#define DC  5             // d chunk size
#define PHIPAD 32         // phi row stride in float2 (256B)
#define DHALF 100         // d's per half
#define CHUNKS 20         // DHALF/DC
#define BUFSZ (K_*DC*PHIPAD)   // float2 per buffer = 3200
#define EPSF 1e-8f

typedef unsigned long long u64;

__device__ __align__(16) float g_phiprob[K_ * D_ * T_];

__device__ __forceinline__ u64 ffma2(u64 a, u64 b, u64 c) {
    u64 d;
    asm("fma.rn.f32x2 %0, %1, %2, %3;" : "=l"(d) : "l"(a), "l"(b), "l"(c));
    return d;
}
__device__ __forceinline__ u64 pack2(float x, float y) {
    u64 r; asm("mov.b64 %0, {%1, %2};" : "=l"(r) : "f"(x), "f"(y)); return r;
}
__device__ __forceinline__ void half_bar(int bar_id) {
    asm volatile("bar.sync %0, %1;" :: "r"(bar_id), "r"(HALF) : "memory");
}
__device__ __forceinline__ void cp_async8(unsigned saddr, const void* gptr) {
    asm volatile("cp.async.ca.shared.global [%0], [%1], 8;" :: "r"(saddr), "l"(gptr) : "memory");
}
__device__ __forceinline__ void cp_commit() {
    asm volatile("cp.async.commit_group;" ::: "memory");
}
__device__ __forceinline__ void cp_wait0() {
    asm volatile("cp.async.wait_group 0;" ::: "memory");
}

__global__ void phi_sigmoid_kernel(const float* __restrict__ phi,
                                   float* __restrict__ out_phi) {
    int i = blockIdx.x * blockDim.x + threadIdx.x;
    if (i < K_ * D_ * T_) {
        float p = __fdividef(1.f, 1.f + __expf(-phi[i]));
        out_phi[i]   = p;
        g_phiprob[i] = p;
    }
}

__global__ __launch_bounds__(BLK, 1) void main_kernel(
    const float* __restrict__ lambda_,
    float* __restrict__ pi_out,
    float* __restrict__ theta_out)
{
    extern __shared__ float2 smem[];   // 4 phi buffers: [half][2][K_][DC][PHIPAD]

    const int tid     = threadIdx.x;
    const int nbase   = blockIdx.x * NT;
    const int halfsel = (tid >= HALF);
    const int ltid    = halfsel ? tid - HALF : tid;
    const int t2c     = ltid % T2;
    const int g       = ltid / T2;          // 0..7 compute, 8 = staging-only
    const bool active = (g < GRP);
    const int bar     = 1 + halfsel;

    float2* buf0 = smem + halfsel * (2 * BUFSZ);
    float2* buf1 = buf0 + BUFSZ;
    const unsigned buf0_u32 = (unsigned)__cvta_generic_to_shared(buf0);
    const unsigned buf1_u32 = (unsigned)__cvta_generic_to_shared(buf1);

    const float2* lam2 = (const float2*)lambda_;
    float2*       th2  = (float2*)theta_out;
    float2*       pi2  = (float2*)pi_out;
    const float2* pp2  = (const float2*)g_phiprob;

    // ---------------- Stage 1: softmax directly into registers ----------------
    u64 th[NNN][K_];
    if (active) {
        #pragma unroll
        for (int i = 0; i < NNN; i++) {
            const int n = nbase + g * NNN + i;
            const size_t base = (size_t)n * K_ * T2 + t2c;

            float2 v[K_];
            #pragma unroll
            for (int k = 0; k < K_; k++) v[k] = lam2[base + (size_t)k * T2];

            float mx = v[0].x, my = v[0].y;
            #pragma unroll
            for (int k = 1; k < K_; k++) { mx = fmaxf(mx, v[k].x); my = fmaxf(my, v[k].y); }

            float sx = 0.f, sy = 0.f;
            #pragma unroll
            for (int k = 0; k < K_; k++) {
                v[k].x = __expf(v[k].x - mx);
                v[k].y = __expf(v[k].y - my);
                sx += v[k].x; sy += v[k].y;
            }
            float ix = __fdividef(1.f, sx), iy = __fdividef(1.f, sy);

            #pragma unroll
            for (int k = 0; k < K_; k++) {
                float tx = v[k].x * ix, ty = v[k].y * iy;
                float2 t; t.x = tx; t.y = ty;
                __stcs(&th2[base + (size_t)k * T2], t);
                th[i][k] = pack2(tx, ty);
            }
        }
    }

    // ---------------- Stage 2: cp.async double-buffered d-chunk loop ----------------
    const int d_base = halfsel * DHALF;

    // Prologue: stage chunk 0 into buf0
    {
        const int d0 = d_base;
        #pragma unroll 1
        for (int i = ltid; i < K_ * DC * T2; i += HALF) {
            int k   = i / (DC * T2);
            int rem = i - k * (DC * T2);
            int d   = rem / T2;
            int t2  = rem - d * T2;
            unsigned dst = buf0_u32 + (unsigned)(((k * DC + d) * PHIPAD + t2) * 8);
            cp_async8(dst, pp2 + (size_t)k * (D_ * T2) + (size_t)d0 * T2 + rem);
        }
        cp_commit();
    }

    for (int c = 0; c < CHUNKS; c++) {
        cp_wait0();
        half_bar(bar);

        // Stage next chunk into the other buffer (overlaps with compute below)
        if (c + 1 < CHUNKS) {
            const int d0n = d_base + (c + 1) * DC;
            unsigned dstbase = ((c + 1) & 1) ? buf1_u32 : buf0_u32;
            #pragma unroll 1
            for (int i = ltid; i < K_ * DC * T2; i += HALF) {
                int k   = i / (DC * T2);
                int rem = i - k * (DC * T2);
                int d   = rem / T2;
                int t2  = rem - d * T2;
                unsigned dst = dstbase + (unsigned)(((k * DC + d) * PHIPAD + t2) * 8);
                cp_async8(dst, pp2 + (size_t)k * (D_ * T2) + (size_t)d0n * T2 + rem);
            }
        }
        cp_commit();

        if (active) {
            const float2* buf = (c & 1) ? buf1 : buf0;
            const int d0 = d_base + c * DC;

            u64 acc[NNN][DC];
            #pragma unroll
            for (int i = 0; i < NNN; i++)
                #pragma unroll
                for (int d = 0; d < DC; d++) acc[i][d] = 0ull;

            #pragma unroll
            for (int k = 0; k < K_; k++) {
                u64 ph[DC];
                #pragma unroll
                for (int d = 0; d < DC; d++)
                    ph[d] = *(const u64*)&buf[(k * DC + d) * PHIPAD + t2c];
                #pragma unroll
                for (int i = 0; i < NNN; i++)
                    #pragma unroll
                    for (int d = 0; d < DC; d++)
                        acc[i][d] = ffma2(th[i][k], ph[d], acc[i][d]);
            }

            const int n0 = nbase + g * NNN;
            float2* pi_base = pi2 + ((size_t)n0 * D_ + d0) * T2 + t2c;
            #pragma unroll
            for (int i = 0; i < NNN; i++) {
                #pragma unroll
                for (int d = 0; d < DC; d++) {
                    float2 f;
                    asm("mov.b64 {%0, %1}, %2;" : "=f"(f.x), "=f"(f.y) : "l"(acc[i][d]));
                    f.x = fminf(fmaxf(f.x, EPSF), 1.f - EPSF);
                    f.y = fminf(fmaxf(f.y, EPSF), 1.f - EPSF);
                    __stcs(&pi_base[((size_t)i * D_ + d) * T2], f);
                }
            }
        }
    }
}

extern "C" void kernel_launch(void* const* d_in, const int* in_sizes, int n_in,
                              void* d_out, int out_size) {
    const float* lambda_ = (const float*)d_in[0];   // [N, K, T]
    const float* phi     = (const float*)d_in[1];   // [K, D, T]

    float* out         = (float*)d_out;
    float* pi_out      = out;                                // 200,000,000
    float* theta_out   = out + (size_t)N_ * D_ * T_;         //  20,000,000
    float* phiprob_out = theta_out + (size_t)N_ * K_ * T_;   //     200,000

    phi_sigmoid_kernel<<<(K_ * D_ * T_ + 255) / 256, 256>>>(phi, phiprob_out);

    size_t smem_bytes = sizeof(float2) * (size_t)(4 * BUFSZ);   // 102400 B
    cudaFuncSetAttribute(main_kernel, cudaFuncAttributeMaxDynamicSharedMemorySize,
                         (int)smem_bytes);
    main_kernel<<<N_ / NT, BLK, smem_bytes>>>(lambda_, pi_out, theta_out);
}